// round 3
// baseline (speedup 1.0000x reference)
#include <cuda_runtime.h>
#include <cooperative_groups.h>

namespace cg = cooperative_groups;

// Problem constants (fixed by the reference)
#define BATCH 128
#define TSTEPS 2048
#define INDIM 32
#define HDIM 256
#define LDIM 16

#define CLS 8          // cluster size = CTAs per batch-group
#define TB 256         // threads per CTA (8 warps)
// Per CTA: 32 hidden columns (HDIM / CLS), 8 batches (BATCH / (gridDim/CLS))

__device__ __forceinline__ unsigned long long pk2(float lo, float hi) {
    return ((unsigned long long)__float_as_uint(hi) << 32) |
           (unsigned long long)__float_as_uint(lo);
}
__device__ __forceinline__ float sum2(unsigned long long v) {
    return __uint_as_float((unsigned int)v) +
           __uint_as_float((unsigned int)(v >> 32));
}
#define FMA2(acc, w, h) \
    asm("fma.rn.f32x2 %0, %1, %2, %0;" : "+l"(acc) : "l"(w), "l"(h))

__device__ __forceinline__ float sigmoidf_(float x) {
    return 1.0f / (1.0f + __expf(-x));
}

__global__ void __cluster_dims__(CLS, 1, 1) __launch_bounds__(TB, 1)
gru_persistent_kernel(const float* __restrict__ xg,      // [B,T,IN]
                      const float* __restrict__ xl,      // [B,T,L]
                      const float* __restrict__ h0,      // [B,H]
                      const float* __restrict__ Wih,     // [3H,IN]
                      const float* __restrict__ Whh,     // [3H,H]
                      const float* __restrict__ bias,    // [3H]
                      const float* __restrict__ bias_n,  // [H]
                      float* __restrict__ out)           // [B,T,1]
{
    // hbuf: full h vector (gathered) per batch. row stride 264 floats (16B-multiple)
    __shared__ float hbuf[8][264];
    __shared__ float xbuf[8][40];
    __shared__ float hpub[2][32][8];            // [buf][local col][batch]
    __shared__ float scratch[8][8][4][32];      // [kchunk][batch][quantity][col]

    cg::cluster_group cluster = cg::this_cluster();
    const int rank = (int)cluster.block_rank();     // 0..7: owns cols [32r,32r+32)
    const int cid  = blockIdx.x / CLS;              // 0..15: owns batches [8c,8c+8)
    const int B0   = cid * 8;
    const int tid  = threadIdx.x;
    const int lane = tid & 31;                      // local hidden column j
    const int warp = tid >> 5;                      // k-chunk (32 k's) / batch in reduce
    const int col  = rank * 32 + lane;              // global hidden column
    const int kbase = warp * 32;

    // ---- Preload recurrent weights into registers, packed (even k, odd k) ----
    unsigned long long wd[3][16];   // Whh[g][col][kbase..kbase+31] as 16 f32x2
    unsigned long long wi[3][2];    // Wih[g][col][warp*4..warp*4+3] as 2 f32x2
#pragma unroll
    for (int g = 0; g < 3; g++) {
        const float* wr = Whh + (size_t)(g * HDIM + col) * HDIM + kbase;
#pragma unroll
        for (int p = 0; p < 16; p++) wd[g][p] = pk2(wr[2 * p], wr[2 * p + 1]);
        const float* wx = Wih + (size_t)(g * HDIM + col) * INDIM + warp * 4;
        wi[g][0] = pk2(wx[0], wx[1]);
        wi[g][1] = pk2(wx[2], wx[3]);
    }
    const float b_r  = bias[col];
    const float b_z  = bias[HDIM + col];
    const float b_ni = bias[2 * HDIM + col];
    const float b_n2 = bias_n[col];

    // ---- Init h from init_hidden (full vector, local copy) ----
    for (int idx = tid; idx < 8 * HDIM; idx += TB) {
        int b = idx >> 8, k = idx & 255;
        hbuf[b][k] = h0[(size_t)(B0 + b) * HDIM + k];
    }
    // ---- Init x[0] ----
    {
        int b = tid >> 5, i = tid & 31;
        xbuf[b][i] = xg[(size_t)(B0 + b) * TSTEPS * INDIM + i];
    }
    __syncthreads();

    // Readout prefetch (rank 0 only; identity: b2 = warp, j = lane)
    float xl_reg = 0.f;
    if (rank == 0 && lane < LDIM)
        xl_reg = xl[(size_t)(B0 + warp) * TSTEPS * LDIM + lane];

    int pbuf = 0;
    for (int t = 0; t < TSTEPS; t++) {
        const int tn = (t + 1 < TSTEPS) ? t + 1 : t;

        // Prefetch next x into a register (latency hidden by the FMA loop)
        float xnext;
        {
            int b = tid >> 5, i = tid & 31;
            xnext = xg[(size_t)(B0 + b) * TSTEPS * INDIM + (size_t)tn * INDIM + i];
        }

        // ---- Recurrent matvec partials: this thread = (col=lane, kchunk=warp) ----
        unsigned long long aR[8], aZ[8], aNh[8], aNi[8];
#pragma unroll
        for (int b = 0; b < 8; b++) { aR[b] = 0ull; aZ[b] = 0ull; aNh[b] = 0ull; aNi[b] = 0ull; }

#pragma unroll
        for (int i = 0; i < 8; i++) {
#pragma unroll
            for (int b = 0; b < 8; b++) {
                // broadcast load: all lanes in warp read the same 16B
                ulonglong2 h2 = *reinterpret_cast<const ulonglong2*>(&hbuf[b][kbase + 4 * i]);
                FMA2(aR[b],  wd[0][2 * i],     h2.x);
                FMA2(aR[b],  wd[0][2 * i + 1], h2.y);
                FMA2(aZ[b],  wd[1][2 * i],     h2.x);
                FMA2(aZ[b],  wd[1][2 * i + 1], h2.y);
                FMA2(aNh[b], wd[2][2 * i],     h2.x);
                FMA2(aNh[b], wd[2][2 * i + 1], h2.y);
            }
        }
        // ---- Input-side partials (x appended: 4 k's per k-chunk) ----
#pragma unroll
        for (int b = 0; b < 8; b++) {
            ulonglong2 x2 = *reinterpret_cast<const ulonglong2*>(&xbuf[b][warp * 4]);
            FMA2(aR[b],  wi[0][0], x2.x); FMA2(aR[b],  wi[0][1], x2.y);
            FMA2(aZ[b],  wi[1][0], x2.x); FMA2(aZ[b],  wi[1][1], x2.y);
            FMA2(aNi[b], wi[2][0], x2.x); FMA2(aNi[b], wi[2][1], x2.y);
        }

        // ---- Store partials (fold even/odd lanes) ----
#pragma unroll
        for (int b = 0; b < 8; b++) {
            scratch[warp][b][0][lane] = sum2(aR[b]);
            scratch[warp][b][1][lane] = sum2(aZ[b]);
            scratch[warp][b][2][lane] = sum2(aNh[b]);
            scratch[warp][b][3][lane] = sum2(aNi[b]);
        }
        __syncthreads();   // S1: partials visible; x-phase reads of xbuf done

        // stash prefetched x (safe: everyone passed x-phase)
        {
            int b = tid >> 5, i = tid & 31;
            xbuf[b][i] = xnext;
        }

        // ---- Reduce + gates: this thread = (batch=warp, col=lane) ----
        float sR = 0.f, sZ = 0.f, sNh = 0.f, sNi = 0.f;
#pragma unroll
        for (int kc = 0; kc < 8; kc++) {
            sR  += scratch[kc][warp][0][lane];
            sZ  += scratch[kc][warp][1][lane];
            sNh += scratch[kc][warp][2][lane];
            sNi += scratch[kc][warp][3][lane];
        }
        const float r = sigmoidf_(sR + b_r);
        const float z = sigmoidf_(sZ + b_z);
        const float n = tanhf(sNi + b_ni + r * (sNh + b_n2));
        const float hprev = hbuf[warp][col];
        const float hn = n + z * (hprev - n);
        hpub[pbuf][lane][warp] = hn;

        // ---- Readout (columns 0..15 live in rank 0) ----
        if (rank == 0) {
            float prod = (lane < LDIM) ? hn * xl_reg : 0.f;
#pragma unroll
            for (int off = 16; off; off >>= 1)
                prod += __shfl_xor_sync(0xffffffffu, prod, off);
            if (lane == 0) out[(size_t)(B0 + warp) * TSTEPS + t] = prod;
            if (lane < LDIM)
                xl_reg = xl[(size_t)(B0 + warp) * TSTEPS * LDIM + (size_t)tn * LDIM + lane];
        }

        cluster.sync();   // release my hpub slice / acquire peers'

        // ---- Gather full h for next step: (src=warp, col=lane) via DSMEM ----
        {
            const int src = warp;
            float* ph = cluster.map_shared_rank(&hpub[pbuf][lane][0], src);
            float4 v0 = *reinterpret_cast<const float4*>(ph);
            float4 v1 = *reinterpret_cast<const float4*>(ph + 4);
            const int c = src * 32 + lane;
            hbuf[0][c] = v0.x; hbuf[1][c] = v0.y; hbuf[2][c] = v0.z; hbuf[3][c] = v0.w;
            hbuf[4][c] = v1.x; hbuf[5][c] = v1.y; hbuf[6][c] = v1.z; hbuf[7][c] = v1.w;
        }
        __syncthreads();   // S2: hbuf/xbuf ready for next step
        pbuf ^= 1;
    }
}

extern "C" void kernel_launch(void* const* d_in, const int* in_sizes, int n_in,
                              void* d_out, int out_size) {
    (void)in_sizes; (void)n_in; (void)out_size;
    const float* xg     = (const float*)d_in[0];  // input_gru   [128,2048,32]
    const float* xl     = (const float*)d_in[1];  // input_linear[128,2048,16]
    const float* h0     = (const float*)d_in[2];  // init_hidden [128,256]
    const float* Wih    = (const float*)d_in[3];  // [768,32]
    const float* Whh    = (const float*)d_in[4];  // [768,256]
    const float* bias   = (const float*)d_in[5];  // [768]
    const float* bias_n = (const float*)d_in[6];  // [256]
    float* out = (float*)d_out;                   // [128,2048,1]

    // 16 clusters x 8 CTAs = 128 CTAs; cluster dims come from __cluster_dims__
    gru_persistent_kernel<<<dim3(BATCH), dim3(TB)>>>(
        xg, xl, h0, Wih, Whh, bias, bias_n, out);
}

// round 4
// speedup vs baseline: 1.0870x; 1.0870x over previous
#include <cuda_runtime.h>
#include <cooperative_groups.h>

namespace cg = cooperative_groups;

// Problem constants (fixed by the reference)
#define BATCH 128
#define TSTEPS 2048
#define INDIM 32
#define HDIM 256
#define LDIM 16

#define CLS 8          // cluster size = CTAs per batch-group
#define TB 256         // threads per CTA (8 warps)

__device__ __forceinline__ unsigned long long pk2(float lo, float hi) {
    return ((unsigned long long)__float_as_uint(hi) << 32) |
           (unsigned long long)__float_as_uint(lo);
}
__device__ __forceinline__ float sum2(unsigned long long v) {
    return __uint_as_float((unsigned int)v) +
           __uint_as_float((unsigned int)(v >> 32));
}
#define FMA2(acc, w, h) \
    asm("fma.rn.f32x2 %0, %1, %2, %0;" : "+l"(acc) : "l"(w), "l"(h))

__device__ __forceinline__ unsigned smem_u32(const void* p) {
    unsigned r;
    asm("{ .reg .u64 t; cvta.to.shared.u64 t, %1; cvt.u32.u64 %0, t; }"
        : "=r"(r) : "l"(p));
    return r;
}

// sigmoid / tanh via MUFU exp + fast reciprocal (~1e-7 rel err, overflow-safe)
__device__ __forceinline__ float fast_sigmoid(float x) {
    return __fdividef(1.0f, 1.0f + __expf(-x));   // exp(-x)->inf => 0, ok
}
__device__ __forceinline__ float fast_tanh(float x) {
    float ex = __expf(2.0f * x);                   // -> inf => tanh=1, ok
    return fmaf(-2.0f, __fdividef(1.0f, ex + 1.0f), 1.0f);
}

__global__ void __cluster_dims__(CLS, 1, 1) __launch_bounds__(TB, 1)
gru_persistent_kernel(const float* __restrict__ xg,      // [B,T,IN]
                      const float* __restrict__ xl,      // [B,T,L]
                      const float* __restrict__ h0,      // [B,H]
                      const float* __restrict__ Wih,     // [3H,IN]
                      const float* __restrict__ Whh,     // [3H,H]
                      const float* __restrict__ bias,    // [3H]
                      const float* __restrict__ bias_n,  // [H]
                      float* __restrict__ out)           // [B,T,1]
{
    __shared__ float  xbuf[8][40];            // [batch][x dim] (+pad)
    __shared__ float  hpub[2][8][32];         // [buf][batch][local col]
    __shared__ float4 scratch[8][8][32];      // [kchunk][batch][col] = {R,Z,Nh,Ni}

    cg::cluster_group cluster = cg::this_cluster();
    const int rank = (int)cluster.block_rank();     // owns cols [32r, 32r+32)
    const int cid  = blockIdx.x / CLS;              // owns batches [8c, 8c+8)
    const int B0   = cid * 8;
    const int tid  = threadIdx.x;
    const int lane = tid & 31;
    const int warp = tid >> 5;                      // FMA phase: k-chunk; gate phase: batch
    const int col  = rank * 32 + lane;              // global hidden column (both phases)
    const int kbase = warp * 32;

    // ---- Recurrent + input weights in registers, packed (even k, odd k) ----
    unsigned long long wd[3][16];   // Whh[g][col][kbase .. kbase+31]
    unsigned long long wi[3][2];    // Wih[g][col][warp*4 .. warp*4+3]
#pragma unroll
    for (int g = 0; g < 3; g++) {
        const float* wr = Whh + (size_t)(g * HDIM + col) * HDIM + kbase;
#pragma unroll
        for (int p = 0; p < 16; p++) wd[g][p] = pk2(wr[2 * p], wr[2 * p + 1]);
        const float* wx = Wih + (size_t)(g * HDIM + col) * INDIM + warp * 4;
        wi[g][0] = pk2(wx[0], wx[1]);
        wi[g][1] = pk2(wx[2], wx[3]);
    }
    const float b_r  = bias[col];
    const float b_z  = bias[HDIM + col];
    const float b_ni = bias[2 * HDIM + col];
    const float b_n2 = bias_n[col];

    // ---- Init: h_prev lives in a register of thread (batch=warp, col) ----
    float hreg = h0[(size_t)(B0 + warp) * HDIM + col];
    hpub[0][warp][lane] = hreg;
    xbuf[warp][lane] = xg[(size_t)(B0 + warp) * TSTEPS * INDIM + lane];

    float xl_reg = 0.f;
    if (rank == 0 && lane < LDIM)
        xl_reg = xl[(size_t)(B0 + warp) * TSTEPS * LDIM + lane];

    __syncthreads();
    cluster.sync();

    // Peer DSMEM base: warp w reads rank w's hpub (its k-chunk of h)
    unsigned peer;
    {
        unsigned loc = smem_u32(&hpub[0][0][0]);
        asm("mapa.shared::cluster.u32 %0, %1, %2;" : "=r"(peer) : "r"(loc), "r"(warp));
    }

    int pbuf = 0;
    for (int t = 0; t < TSTEPS; t++) {
        const int tn = (t + 1 < TSTEPS) ? t + 1 : t;

        // Prefetch next x (latency hidden under the FMA loop)
        float xnext = xg[(size_t)(B0 + warp) * TSTEPS * INDIM +
                         (size_t)tn * INDIM + lane];

        // ---- Matvec partials: thread = (col=lane, kchunk=warp) ----
        unsigned long long aR[8], aZ[8], aNh[8], aNi[8];
#pragma unroll
        for (int b = 0; b < 8; b++) { aR[b] = 0ull; aZ[b] = 0ull; aNh[b] = 0ull; aNi[b] = 0ull; }

        // input-side (local smem, fast) first — DSMEM loads below get batched
#pragma unroll
        for (int b = 0; b < 8; b++) {
            ulonglong2 x2 = *reinterpret_cast<const ulonglong2*>(&xbuf[b][warp * 4]);
            FMA2(aR[b],  wi[0][0], x2.x); FMA2(aR[b],  wi[0][1], x2.y);
            FMA2(aZ[b],  wi[1][0], x2.x); FMA2(aZ[b],  wi[1][1], x2.y);
            FMA2(aNi[b], wi[2][0], x2.x); FMA2(aNi[b], wi[2][1], x2.y);
        }

        // recurrent side: read peer hpub[pbuf] directly via DSMEM (broadcast per warp)
        const unsigned pbase = peer + (unsigned)(pbuf * 1024);  // 256 floats
#pragma unroll
        for (int i = 0; i < 8; i++) {
            unsigned long long hx[8], hy[8];
#pragma unroll
            for (int b = 0; b < 8; b++) {
                unsigned a = pbase + (unsigned)(b * 128 + i * 16);
                asm volatile("ld.shared::cluster.v2.b64 {%0, %1}, [%2];"
                             : "=l"(hx[b]), "=l"(hy[b]) : "r"(a));
            }
#pragma unroll
            for (int b = 0; b < 8; b++) {
                FMA2(aR[b],  wd[0][2 * i],     hx[b]);
                FMA2(aR[b],  wd[0][2 * i + 1], hy[b]);
                FMA2(aZ[b],  wd[1][2 * i],     hx[b]);
                FMA2(aZ[b],  wd[1][2 * i + 1], hy[b]);
                FMA2(aNh[b], wd[2][2 * i],     hx[b]);
                FMA2(aNh[b], wd[2][2 * i + 1], hy[b]);
            }
        }

        // ---- Store partials: one STS.128 per batch (8 per thread) ----
#pragma unroll
        for (int b = 0; b < 8; b++) {
            scratch[warp][b][lane] = make_float4(sum2(aR[b]), sum2(aZ[b]),
                                                 sum2(aNh[b]), sum2(aNi[b]));
        }
        __syncthreads();   // S1: partials visible; xbuf reads complete

        xbuf[warp][lane] = xnext;   // safe: all xbuf readers passed S1

        // ---- Reduce + gates: thread = (batch=warp, col=lane) ----
        float sR = 0.f, sZ = 0.f, sNh = 0.f, sNi = 0.f;
#pragma unroll
        for (int kc = 0; kc < 8; kc++) {
            float4 v = scratch[kc][warp][lane];
            sR += v.x; sZ += v.y; sNh += v.z; sNi += v.w;
        }
        const float r = fast_sigmoid(sR + b_r);
        const float z = fast_sigmoid(sZ + b_z);
        const float n = fast_tanh(sNi + b_ni + r * (sNh + b_n2));
        hreg = n + z * (hreg - n);
        hpub[pbuf ^ 1][warp][lane] = hreg;

        // release my h slice; overlap readout with barrier skew
        asm volatile("barrier.cluster.arrive.aligned;" ::: "memory");

        if (rank == 0) {   // readout: columns 0..15 live here
            float prod = (lane < LDIM) ? hreg * xl_reg : 0.f;
#pragma unroll
            for (int off = 16; off; off >>= 1)
                prod += __shfl_xor_sync(0xffffffffu, prod, off);
            if (lane == 0) out[(size_t)(B0 + warp) * TSTEPS + t] = prod;
            if (lane < LDIM)
                xl_reg = xl[(size_t)(B0 + warp) * TSTEPS * LDIM +
                            (size_t)tn * LDIM + lane];
        }

        asm volatile("barrier.cluster.wait.aligned;" ::: "memory");
        pbuf ^= 1;
    }
}

extern "C" void kernel_launch(void* const* d_in, const int* in_sizes, int n_in,
                              void* d_out, int out_size) {
    (void)in_sizes; (void)n_in; (void)out_size;
    const float* xg     = (const float*)d_in[0];  // input_gru   [128,2048,32]
    const float* xl     = (const float*)d_in[1];  // input_linear[128,2048,16]
    const float* h0     = (const float*)d_in[2];  // init_hidden [128,256]
    const float* Wih    = (const float*)d_in[3];  // [768,32]
    const float* Whh    = (const float*)d_in[4];  // [768,256]
    const float* bias   = (const float*)d_in[5];  // [768]
    const float* bias_n = (const float*)d_in[6];  // [256]
    float* out = (float*)d_out;                   // [128,2048,1]

    gru_persistent_kernel<<<dim3(BATCH), dim3(TB)>>>(
        xg, xl, h0, Wih, Whh, bias, bias_n, out);
}

// round 6
// speedup vs baseline: 1.4567x; 1.3401x over previous
#include <cuda_runtime.h>
#include <cooperative_groups.h>

namespace cg = cooperative_groups;

// Problem constants (fixed by the reference)
#define BATCH 128
#define TSTEPS 2048
#define INDIM 32
#define HDIM 256
#define LDIM 16

#define CLS 8          // cluster size = CTAs per batch-group
#define TB 256         // threads per CTA (8 warps)

struct Smem {
    float hbuf[2][8][256];              // [buf][batch][col] FULL h, local copy
    float4 scratch[8][8][32];           // [kchunk][batch][col] {R,Z,Nh,Ni}
    float xbuf[8][40];                  // [batch][x dim] (+pad)
    unsigned long long mbars[2];
};
#define SMEM_BYTES ((int)sizeof(Smem))

__device__ __forceinline__ unsigned long long pk2(float lo, float hi) {
    return ((unsigned long long)__float_as_uint(hi) << 32) |
           (unsigned long long)__float_as_uint(lo);
}
__device__ __forceinline__ float sum2(unsigned long long v) {
    return __uint_as_float((unsigned int)v) +
           __uint_as_float((unsigned int)(v >> 32));
}
#define FMA2(acc, w, h) \
    asm("fma.rn.f32x2 %0, %1, %2, %0;" : "+l"(acc) : "l"(w), "l"(h))

__device__ __forceinline__ unsigned smem_u32(const void* p) {
    unsigned r;
    asm("{ .reg .u64 t; cvta.to.shared.u64 t, %1; cvt.u32.u64 %0, t; }"
        : "=r"(r) : "l"(p));
    return r;
}

__device__ __forceinline__ float fast_sigmoid(float x) {
    return __fdividef(1.0f, 1.0f + __expf(-x));
}
__device__ __forceinline__ float fast_tanh(float x) {
    float ex = __expf(2.0f * x);
    return fmaf(-2.0f, __fdividef(1.0f, ex + 1.0f), 1.0f);
}

__device__ __forceinline__ void mbar_wait(unsigned addr, unsigned parity) {
    asm volatile(
        "{\n\t"
        ".reg .pred P;\n\t"
        "WL_%=:\n\t"
        "mbarrier.try_wait.parity.acquire.cta.shared::cta.b64 P, [%0], %1, 0x989680;\n\t"
        "@P bra.uni WD_%=;\n\t"
        "bra.uni WL_%=;\n\t"
        "WD_%=:\n\t"
        "}"
        :: "r"(addr), "r"(parity) : "memory");
}

__global__ void __cluster_dims__(CLS, 1, 1) __launch_bounds__(TB, 1)
gru_persistent_kernel(const float* __restrict__ xg,      // [B,T,IN]
                      const float* __restrict__ xl,      // [B,T,L]
                      const float* __restrict__ h0,      // [B,H]
                      const float* __restrict__ Wih,     // [3H,IN]
                      const float* __restrict__ Whh,     // [3H,H]
                      const float* __restrict__ bias,    // [3H]
                      const float* __restrict__ bias_n,  // [H]
                      float* __restrict__ out)           // [B,T,1]
{
    extern __shared__ __align__(16) char dynsmem[];
    Smem& sm = *reinterpret_cast<Smem*>(dynsmem);

    cg::cluster_group cluster = cg::this_cluster();
    const int rank = (int)cluster.block_rank();     // owns cols [32r, 32r+32)
    const int cid  = blockIdx.x / CLS;              // owns batches [8c, 8c+8)
    const int B0   = cid * 8;
    const int tid  = threadIdx.x;
    const int lane = tid & 31;
    const int warp = tid >> 5;      // FMA phase: k-chunk; gate/send phase: batch
    const int col  = rank * 32 + lane;
    const int kbase = warp * 32;

    // ---- Weights in registers, packed (even k, odd k) ----
    unsigned long long wd[3][16];   // Whh[g][col][kbase .. kbase+31]
    unsigned long long wi[3][2];    // Wih[g][col][warp*4 .. warp*4+3]
#pragma unroll
    for (int g = 0; g < 3; g++) {
        const float* wr = Whh + (size_t)(g * HDIM + col) * HDIM + kbase;
#pragma unroll
        for (int p = 0; p < 16; p++) wd[g][p] = pk2(wr[2 * p], wr[2 * p + 1]);
        const float* wx = Wih + (size_t)(g * HDIM + col) * INDIM + warp * 4;
        wi[g][0] = pk2(wx[0], wx[1]);
        wi[g][1] = pk2(wx[2], wx[3]);
    }
    const float b_r  = bias[col];
    const float b_z  = bias[HDIM + col];
    const float b_ni = bias[2 * HDIM + col];
    const float b_n2 = bias_n[col];

    const unsigned mloc = smem_u32(&sm.mbars[0]);
    if (tid == 0) {
        asm volatile("mbarrier.init.shared.b64 [%0], 1;" :: "r"(mloc)     : "memory");
        asm volatile("mbarrier.init.shared.b64 [%0], 1;" :: "r"(mloc + 8) : "memory");
    }

    // ---- Init: local full h0 copy (buffer 0) ----
    for (int idx = tid; idx < 8 * HDIM; idx += TB) {
        int b = idx >> 8, k = idx & 255;
        sm.hbuf[0][b][k] = h0[(size_t)(B0 + b) * HDIM + k];
    }
    sm.xbuf[warp][lane] = xg[(size_t)(B0 + warp) * TSTEPS * INDIM + lane];

    float hreg = h0[(size_t)(B0 + warp) * HDIM + col];   // h_prev for (batch=warp,col)
    float xl_reg = 0.f;
    if (rank == 0 && lane < LDIM)
        xl_reg = xl[(size_t)(B0 + warp) * TSTEPS * LDIM + lane];

    __syncthreads();
    cluster.sync();    // peers' mbarriers initialized before any st.async lands

    if (tid == 0) {
        // complete mbar[0] phase 0 immediately (buffer 0 pre-filled locally)
        asm volatile("mbarrier.arrive.shared.b64 _, [%0];" :: "r"(mloc) : "memory");
        // arm mbar[1] for step 1 (expects full h push: 8 KB)
        asm volatile("mbarrier.arrive.expect_tx.shared.b64 _, [%0], %1;"
                     :: "r"(mloc + 8), "r"(8192u) : "memory");
    }

    // Peer base addresses (data + mbar) for the push
    unsigned pb[8], pm[8];
    {
        unsigned hb = smem_u32(&sm.hbuf[0][0][0]);
#pragma unroll
        for (int k = 0; k < 8; k++) {
            asm("mapa.shared::cluster.u32 %0, %1, %2;" : "=r"(pb[k]) : "r"(hb),   "r"(k));
            asm("mapa.shared::cluster.u32 %0, %1, %2;" : "=r"(pm[k]) : "r"(mloc), "r"(k));
        }
    }
    const unsigned soff = (unsigned)((warp * 256 + col) * 4);  // my slot in a buffer

    for (int t = 0; t < TSTEPS; t++) {
        const int buf = t & 1;
        const unsigned par = (unsigned)((t >> 1) & 1);

        mbar_wait(mloc + (unsigned)(buf * 8), par);   // full h for this step local

        // Re-arm this buffer's mbar for step t+2 (before any of this CTA's own
        // sends this step; peers can't target it before our S1-chain anyway).
        if (tid == 0 && t + 2 < TSTEPS) {
            asm volatile("mbarrier.arrive.expect_tx.shared.b64 _, [%0], %1;"
                         :: "r"(mloc + (unsigned)(buf * 8)), "r"(8192u) : "memory");
        }

        const int tn = (t + 1 < TSTEPS) ? t + 1 : t;
        float xnext = xg[(size_t)(B0 + warp) * TSTEPS * INDIM +
                         (size_t)tn * INDIM + lane];

        // ---- Matvec partials: thread = (col=lane, kchunk=warp) ----
        unsigned long long aR[8], aZ[8], aNh[8], aNi[8];
#pragma unroll
        for (int b = 0; b < 8; b++) { aR[b] = 0ull; aZ[b] = 0ull; aNh[b] = 0ull; aNi[b] = 0ull; }

#pragma unroll
        for (int b = 0; b < 8; b++) {
            ulonglong2 x2 = *reinterpret_cast<const ulonglong2*>(&sm.xbuf[b][warp * 4]);
            FMA2(aR[b],  wi[0][0], x2.x); FMA2(aR[b],  wi[0][1], x2.y);
            FMA2(aZ[b],  wi[1][0], x2.x); FMA2(aZ[b],  wi[1][1], x2.y);
            FMA2(aNi[b], wi[2][0], x2.x); FMA2(aNi[b], wi[2][1], x2.y);
        }

#pragma unroll
        for (int i = 0; i < 8; i++) {
#pragma unroll
            for (int b = 0; b < 8; b++) {
                // local broadcast load: all lanes read the same 16B
                ulonglong2 h2 = *reinterpret_cast<const ulonglong2*>(
                    &sm.hbuf[buf][b][kbase + 4 * i]);
                FMA2(aR[b],  wd[0][2 * i],     h2.x);
                FMA2(aR[b],  wd[0][2 * i + 1], h2.y);
                FMA2(aZ[b],  wd[1][2 * i],     h2.x);
                FMA2(aZ[b],  wd[1][2 * i + 1], h2.y);
                FMA2(aNh[b], wd[2][2 * i],     h2.x);
                FMA2(aNh[b], wd[2][2 * i + 1], h2.y);
            }
        }

        // ---- Partials: one STS.128 per batch ----
#pragma unroll
        for (int b = 0; b < 8; b++) {
            sm.scratch[warp][b][lane] = make_float4(sum2(aR[b]), sum2(aZ[b]),
                                                    sum2(aNh[b]), sum2(aNi[b]));
        }
        __syncthreads();   // S1: partials visible; hbuf/xbuf reads of this step done

        sm.xbuf[warp][lane] = xnext;   // readers passed S1

        // ---- Reduce + gates: thread = (batch=warp, col=lane) ----
        float sR = 0.f, sZ = 0.f, sNh = 0.f, sNi = 0.f;
#pragma unroll
        for (int kc = 0; kc < 8; kc++) {
            float4 v = sm.scratch[kc][warp][lane];
            sR += v.x; sZ += v.y; sNh += v.z; sNi += v.w;
        }
        const float r = fast_sigmoid(sR + b_r);
        const float z = fast_sigmoid(sZ + b_z);
        const float n = fast_tanh(sNi + b_ni + r * (sNh + b_n2));
        hreg = n + z * (hreg - n);

        // ---- Push my h value into every CTA's hbuf[buf^1] (8 x 4B st.async) ----
        if (t + 1 < TSTEPS) {
            const unsigned doff = soff + (unsigned)((buf ^ 1) * 8192);
            const unsigned moff = (unsigned)((buf ^ 1) * 8);
            const unsigned hval = __float_as_uint(hreg);
#pragma unroll
            for (int k = 0; k < 8; k++) {
                asm volatile(
                    "st.async.weak.shared::cluster.mbarrier::complete_tx::bytes.b32 "
                    "[%0], %1, [%2];"
                    :: "r"(pb[k] + doff), "r"(hval), "r"(pm[k] + moff) : "memory");
            }
        }

        // ---- Readout (columns 0..15 live in rank 0) ----
        if (rank == 0) {
            float prod = (lane < LDIM) ? hreg * xl_reg : 0.f;
#pragma unroll
            for (int off = 16; off; off >>= 1)
                prod += __shfl_xor_sync(0xffffffffu, prod, off);
            if (lane == 0) out[(size_t)(B0 + warp) * TSTEPS + t] = prod;
            if (lane < LDIM)
                xl_reg = xl[(size_t)(B0 + warp) * TSTEPS * LDIM +
                            (size_t)tn * LDIM + lane];
        }

        __syncthreads();   // S2: xbuf/scratch safe to recycle next step
    }

    cluster.sync();   // clean distributed exit
}

extern "C" void kernel_launch(void* const* d_in, const int* in_sizes, int n_in,
                              void* d_out, int out_size) {
    (void)in_sizes; (void)n_in; (void)out_size;
    const float* xg     = (const float*)d_in[0];  // input_gru   [128,2048,32]
    const float* xl     = (const float*)d_in[1];  // input_linear[128,2048,16]
    const float* h0     = (const float*)d_in[2];  // init_hidden [128,256]
    const float* Wih    = (const float*)d_in[3];  // [768,32]
    const float* Whh    = (const float*)d_in[4];  // [768,256]
    const float* bias   = (const float*)d_in[5];  // [768]
    const float* bias_n = (const float*)d_in[6];  // [256]
    float* out = (float*)d_out;                   // [128,2048,1]

    // >48KB smem needs the opt-in attribute (idempotent; not an allocation)
    cudaFuncSetAttribute(gru_persistent_kernel,
                         cudaFuncAttributeMaxDynamicSharedMemorySize, SMEM_BYTES);

    gru_persistent_kernel<<<dim3(BATCH), dim3(TB), SMEM_BYTES>>>(
        xg, xl, h0, Wih, Whh, bias, bias_n, out);
}

// round 7
// speedup vs baseline: 1.4925x; 1.0246x over previous
#include <cuda_runtime.h>
#include <cooperative_groups.h>

namespace cg = cooperative_groups;

// Problem constants (fixed by the reference)
#define BATCH 128
#define TSTEPS 2048
#define INDIM 32
#define HDIM 256
#define LDIM 16

#define CLS 8          // cluster size = CTAs per batch-group
#define TB 256         // threads per CTA (8 warps)

struct Smem {
    float hbuf[2][8][8][32];            // [buf][src rank][batch][lane]  (1KB per src)
    float4 scratch[8][8][32];           // [kchunk][batch][col] {R,Z,Nh,Ni}
    float xbuf[8][40];                  // [batch][x dim] (+pad)
    unsigned long long mbars[2];
};
#define SMEM_BYTES ((int)sizeof(Smem))

__device__ __forceinline__ unsigned long long pk2(float lo, float hi) {
    return ((unsigned long long)__float_as_uint(hi) << 32) |
           (unsigned long long)__float_as_uint(lo);
}
__device__ __forceinline__ float sum2(unsigned long long v) {
    return __uint_as_float((unsigned int)v) +
           __uint_as_float((unsigned int)(v >> 32));
}
#define FMA2(acc, w, h) \
    asm("fma.rn.f32x2 %0, %1, %2, %0;" : "+l"(acc) : "l"(w), "l"(h))

__device__ __forceinline__ unsigned smem_u32(const void* p) {
    unsigned r;
    asm("{ .reg .u64 t; cvta.to.shared.u64 t, %1; cvt.u32.u64 %0, t; }"
        : "=r"(r) : "l"(p));
    return r;
}

__device__ __forceinline__ float fast_sigmoid(float x) {
    return __fdividef(1.0f, 1.0f + __expf(-x));
}
__device__ __forceinline__ float fast_tanh(float x) {
    float ex = __expf(2.0f * x);
    return fmaf(-2.0f, __fdividef(1.0f, ex + 1.0f), 1.0f);
}

__device__ __forceinline__ void mbar_wait(unsigned addr, unsigned parity) {
    asm volatile(
        "{\n\t"
        ".reg .pred P;\n\t"
        "WL_%=:\n\t"
        "mbarrier.try_wait.parity.acquire.cta.shared::cta.b64 P, [%0], %1, 0x989680;\n\t"
        "@P bra.uni WD_%=;\n\t"
        "bra.uni WL_%=;\n\t"
        "WD_%=:\n\t"
        "}"
        :: "r"(addr), "r"(parity) : "memory");
}

__global__ void __cluster_dims__(CLS, 1, 1) __launch_bounds__(TB, 1)
gru_persistent_kernel(const float* __restrict__ xg,      // [B,T,IN]
                      const float* __restrict__ xl,      // [B,T,L]
                      const float* __restrict__ h0,      // [B,H]
                      const float* __restrict__ Wih,     // [3H,IN]
                      const float* __restrict__ Whh,     // [3H,H]
                      const float* __restrict__ bias,    // [3H]
                      const float* __restrict__ bias_n,  // [H]
                      float* __restrict__ out)           // [B,T,1]
{
    extern __shared__ __align__(16) char dynsmem[];
    Smem& sm = *reinterpret_cast<Smem*>(dynsmem);

    cg::cluster_group cluster = cg::this_cluster();
    const int rank = (int)cluster.block_rank();     // owns cols [32r, 32r+32)
    const int cid  = blockIdx.x / CLS;              // owns batches [8c, 8c+8)
    const int B0   = cid * 8;
    const int tid  = threadIdx.x;
    const int lane = tid & 31;
    const int warp = tid >> 5;      // FMA phase: k-chunk (= src rank); gate phase: batch
    const int col  = rank * 32 + lane;
    const int kbase = warp * 32;

    // ---- Weights in registers, packed (even k, odd k) ----
    unsigned long long wd[3][16];   // Whh[g][col][kbase .. kbase+31]
    unsigned long long wi[3][2];    // Wih[g][col][warp*4 .. warp*4+3]
#pragma unroll
    for (int g = 0; g < 3; g++) {
        const float* wr = Whh + (size_t)(g * HDIM + col) * HDIM + kbase;
#pragma unroll
        for (int p = 0; p < 16; p++) wd[g][p] = pk2(wr[2 * p], wr[2 * p + 1]);
        const float* wx = Wih + (size_t)(g * HDIM + col) * INDIM + warp * 4;
        wi[g][0] = pk2(wx[0], wx[1]);
        wi[g][1] = pk2(wx[2], wx[3]);
    }
    const float b_r  = bias[col];
    const float b_z  = bias[HDIM + col];
    const float b_ni = bias[2 * HDIM + col];
    const float b_n2 = bias_n[col];

    const unsigned mloc = smem_u32(&sm.mbars[0]);
    const unsigned hloc = smem_u32(&sm.hbuf[0][0][0][0]);
    if (tid == 0) {
        asm volatile("mbarrier.init.shared.b64 [%0], 1;" :: "r"(mloc)     : "memory");
        asm volatile("mbarrier.init.shared.b64 [%0], 1;" :: "r"(mloc + 8) : "memory");
    }

    // ---- Init: buffer 0 holds full h0, laid out [src][batch][lane] ----
    for (int idx = tid; idx < 8 * HDIM; idx += TB) {
        int src = idx >> 8, b = (idx >> 5) & 7, l = idx & 31;
        sm.hbuf[0][src][b][l] = h0[(size_t)(B0 + b) * HDIM + src * 32 + l];
    }
    sm.xbuf[warp][lane] = xg[(size_t)(B0 + warp) * TSTEPS * INDIM + lane];

    float hreg = h0[(size_t)(B0 + warp) * HDIM + col];   // h_prev for (batch=warp,col)
    float xl_reg = 0.f;
    if (rank == 0 && lane < LDIM)
        xl_reg = xl[(size_t)(B0 + warp) * TSTEPS * LDIM + lane];

    __syncthreads();
    cluster.sync();    // peers' mbarriers initialized before any bulk copy lands

    if (tid == 0) {
        // complete mbar[0] phase 0 (buffer 0 pre-filled locally)
        asm volatile("mbarrier.arrive.shared.b64 _, [%0];" :: "r"(mloc) : "memory");
        // arm mbar[1] for step 1: expects 7 peers x 1KB
        asm volatile("mbarrier.arrive.expect_tx.shared.b64 _, [%0], %1;"
                     :: "r"(mloc + 8), "r"(7168u) : "memory");
    }

    // Peer base addresses (hbuf + mbar)
    unsigned pb[8], pm[8];
#pragma unroll
    for (int k = 0; k < 8; k++) {
        asm("mapa.shared::cluster.u32 %0, %1, %2;" : "=r"(pb[k]) : "r"(hloc), "r"(k));
        asm("mapa.shared::cluster.u32 %0, %1, %2;" : "=r"(pm[k]) : "r"(mloc), "r"(k));
    }

    for (int t = 0; t < TSTEPS; t++) {
        const int buf = t & 1;
        const unsigned par = (unsigned)((t >> 1) & 1);

        mbar_wait(mloc + (unsigned)(buf * 8), par);   // full h for this step local

        // Re-arm this buffer's mbar for step t+2
        if (tid == 0 && t + 2 < TSTEPS) {
            asm volatile("mbarrier.arrive.expect_tx.shared.b64 _, [%0], %1;"
                         :: "r"(mloc + (unsigned)(buf * 8)), "r"(7168u) : "memory");
        }

        const int tn = (t + 1 < TSTEPS) ? t + 1 : t;
        float xnext = xg[(size_t)(B0 + warp) * TSTEPS * INDIM +
                         (size_t)tn * INDIM + lane];

        // ---- Matvec partials: thread = (col=lane, kchunk=warp) ----
        unsigned long long aR[8], aZ[8], aNh[8], aNi[8];
#pragma unroll
        for (int b = 0; b < 8; b++) { aR[b] = 0ull; aZ[b] = 0ull; aNh[b] = 0ull; aNi[b] = 0ull; }

#pragma unroll
        for (int b = 0; b < 8; b++) {
            ulonglong2 x2 = *reinterpret_cast<const ulonglong2*>(&sm.xbuf[b][warp * 4]);
            FMA2(aR[b],  wi[0][0], x2.x); FMA2(aR[b],  wi[0][1], x2.y);
            FMA2(aZ[b],  wi[1][0], x2.x); FMA2(aZ[b],  wi[1][1], x2.y);
            FMA2(aNi[b], wi[2][0], x2.x); FMA2(aNi[b], wi[2][1], x2.y);
        }

#pragma unroll
        for (int i = 0; i < 8; i++) {
#pragma unroll
            for (int b = 0; b < 8; b++) {
                // local broadcast load: all lanes read the same 16B
                // warp's k-chunk == src rank 'warp' block
                ulonglong2 h2 = *reinterpret_cast<const ulonglong2*>(
                    &sm.hbuf[buf][warp][b][4 * i]);
                FMA2(aR[b],  wd[0][2 * i],     h2.x);
                FMA2(aR[b],  wd[0][2 * i + 1], h2.y);
                FMA2(aZ[b],  wd[1][2 * i],     h2.x);
                FMA2(aZ[b],  wd[1][2 * i + 1], h2.y);
                FMA2(aNh[b], wd[2][2 * i],     h2.x);
                FMA2(aNh[b], wd[2][2 * i + 1], h2.y);
            }
        }

        // ---- Partials: one STS.128 per batch ----
#pragma unroll
        for (int b = 0; b < 8; b++) {
            sm.scratch[warp][b][lane] = make_float4(sum2(aR[b]), sum2(aZ[b]),
                                                    sum2(aNh[b]), sum2(aNi[b]));
        }
        __syncthreads();   // S1: partials visible; hbuf/xbuf reads of this step done

        sm.xbuf[warp][lane] = xnext;   // readers passed S1

        // ---- Reduce + gates: thread = (batch=warp, col=lane) ----
        float sR = 0.f, sZ = 0.f, sNh = 0.f, sNi = 0.f;
#pragma unroll
        for (int kc = 0; kc < 8; kc++) {
            float4 v = sm.scratch[kc][warp][lane];
            sR += v.x; sZ += v.y; sNh += v.z; sNi += v.w;
        }
        const float r = fast_sigmoid(sR + b_r);
        const float z = fast_sigmoid(sZ + b_z);
        const float n = fast_tanh(sNi + b_ni + r * (sNh + b_n2));
        hreg = n + z * (hreg - n);

        // Stage my h into my own block of the next buffer (also serves local use)
        sm.hbuf[buf ^ 1][rank][warp][lane] = hreg;

        __syncthreads();   // S2: stage complete; scratch/xbuf safe to recycle

        // ---- One 1KB bulk copy per peer (lanes 0..7 of warp 0, self skipped) ----
        if (t + 1 < TSTEPS && tid < 8 && tid != rank) {
            asm volatile("fence.proxy.async.shared::cta;" ::: "memory");
            const unsigned off = (unsigned)((buf ^ 1) * 8192 + rank * 1024);
            asm volatile(
                "cp.async.bulk.shared::cluster.shared::cta.mbarrier::complete_tx::bytes "
                "[%0], [%1], %2, [%3];"
                :: "r"(pb[tid] + off), "r"(hloc + off), "r"(1024u),
                   "r"(pm[tid] + (unsigned)((buf ^ 1) * 8)) : "memory");
        }

        // ---- Readout (columns 0..15 live in rank 0) ----
        if (rank == 0) {
            float prod = (lane < LDIM) ? hreg * xl_reg : 0.f;
#pragma unroll
            for (int off = 16; off; off >>= 1)
                prod += __shfl_xor_sync(0xffffffffu, prod, off);
            if (lane == 0) out[(size_t)(B0 + warp) * TSTEPS + t] = prod;
            if (lane < LDIM)
                xl_reg = xl[(size_t)(B0 + warp) * TSTEPS * LDIM +
                            (size_t)tn * LDIM + lane];
        }
    }

    cluster.sync();   // clean distributed exit
}

extern "C" void kernel_launch(void* const* d_in, const int* in_sizes, int n_in,
                              void* d_out, int out_size) {
    (void)in_sizes; (void)n_in; (void)out_size;
    const float* xg     = (const float*)d_in[0];  // input_gru   [128,2048,32]
    const float* xl     = (const float*)d_in[1];  // input_linear[128,2048,16]
    const float* h0     = (const float*)d_in[2];  // init_hidden [128,256]
    const float* Wih    = (const float*)d_in[3];  // [768,32]
    const float* Whh    = (const float*)d_in[4];  // [768,256]
    const float* bias   = (const float*)d_in[5];  // [768]
    const float* bias_n = (const float*)d_in[6];  // [256]
    float* out = (float*)d_out;                   // [128,2048,1]

    cudaFuncSetAttribute(gru_persistent_kernel,
                         cudaFuncAttributeMaxDynamicSharedMemorySize, SMEM_BYTES);

    gru_persistent_kernel<<<dim3(BATCH), dim3(TB), SMEM_BYTES>>>(
        xg, xl, h0, Wih, Whh, bias, bias_n, out);
}